// round 9
// baseline (speedup 1.0000x reference)
#include <cuda_runtime.h>
#include <cuda_bf16.h>
#include <cstdint>

// ---------------- problem constants ----------------
#define BATCH 32
#define SEQ   2048
#define NROWS (BATCH*SEQ)   // 65536
#define NP 256              // packed columns: 8 head-groups x (19 cult | 10 moral | 3 pad)

// ---------------- scratch (device globals) ----------------
__device__ __nv_bfloat16 g_P1T[NP*1024];               // B of pass 1: [n][k]
__device__ __nv_bfloat16 g_GT[NP*NP];                  // B of pass 2: GT[n_out][n_in]
__device__ float g_KQ[512*NP];                         // KQ[e][n] (includes 1/8)
__device__ float g_VW[NP*512];                         // VWo[n][f]
__device__ float g_beta1[NP], g_beta2[NP];
__device__ float g_Kc[19*512], g_Vc[19*512], g_Km[10*512], g_Vm[10*512];
__device__ float g_bf1[1024];
__device__ float g_bf2c[512], g_bf2m[512];
__device__ float g_pmsum[BATCH];
__device__ float g_part[512*NP];

__device__ __forceinline__ uint32_t smem_u32(const void* p) {
    return (uint32_t)__cvta_generic_to_shared(p);
}
__device__ __forceinline__ void cp_async16(uint32_t dst, const void* src) {
    asm volatile("cp.async.cg.shared.global [%0], [%1], 16;" :: "r"(dst), "l"(src));
}
__device__ __forceinline__ uint32_t sw128(uint32_t b) { return b ^ ((b >> 3) & 0x70u); }
__device__ __forceinline__ uint32_t pk2(float x, float y) {
    __nv_bfloat162 h = __floats2bfloat162_rn(x, y);
    return *reinterpret_cast<uint32_t*>(&h);
}

// ===================================================================
// prep level A: K/V head tables + folded bias rows + pmsum
// ===================================================================
__global__ void prep_ab(const float* __restrict__ ctab, const float* __restrict__ mtab,
                        const float* __restrict__ cWk, const float* __restrict__ cbk,
                        const float* __restrict__ cWv, const float* __restrict__ cbv,
                        const float* __restrict__ mWk, const float* __restrict__ mbk,
                        const float* __restrict__ mWv, const float* __restrict__ mbv,
                        const float* __restrict__ b_lin,
                        const float* __restrict__ cWq, const float* __restrict__ cbq,
                        const float* __restrict__ mWq, const float* __restrict__ mbq,
                        const float* __restrict__ cbo, const float* __restrict__ mbo,
                        const int* __restrict__ em, const int* __restrict__ pmask)
{
    const int id = blockIdx.x;
    const int tid = threadIdx.x;
    if (id < 62) {
        const float* arow; const float* W; const float* bb; float* out;
        if      (id < 19)  { arow = ctab + id * 512;        W = cWk; bb = cbk; out = g_Kc + id * 512; }
        else if (id < 38)  { arow = ctab + (id - 19) * 512; W = cWv; bb = cbv; out = g_Vc + (id - 19) * 512; }
        else if (id < 48)  { arow = mtab + (id - 38) * 512; W = mWk; bb = mbk; out = g_Km + (id - 38) * 512; }
        else if (id < 58)  { arow = mtab + (id - 48) * 512; W = mWv; bb = mbv; out = g_Vm + (id - 48) * 512; }
        else if (id == 58) { arow = b_lin; W = cWq; bb = cbq; out = g_bf1; }
        else if (id == 59) { arow = b_lin; W = mWq; bb = mbq; out = g_bf1 + 512; }
        else if (id == 60) { arow = cbo;   W = cWq; bb = cbq; out = g_bf2c; }
        else               { arow = mbo;   W = mWq; bb = mbq; out = g_bf2m; }

        __shared__ float sA[512];
        sA[tid] = arow[tid];
        __syncthreads();
        float acc = bb[tid];
        for (int k = 0; k < 512; k++) acc += sA[k] * W[k * 512 + tid];
        out[tid] = acc;
    } else {
        const int b = id - 62;
        __shared__ int sred[16];
        int cnt = 0;
        for (int s = tid; s < SEQ; s += 512) cnt += em[b * SEQ + s] * pmask[b * SEQ + s];
#pragma unroll
        for (int st = 16; st; st >>= 1) cnt += __shfl_xor_sync(0xffffffffu, cnt, st);
        if ((tid & 31) == 0) sred[tid >> 5] = cnt;
        __syncthreads();
        if (tid == 0) {
            int tot = 0;
            for (int w = 0; w < 16; w++) tot += sred[w];
            g_pmsum[b] = (float)tot;
        }
    }
}

// ===================================================================
// prep level B: kq (ids 0..511), vwo (ids 512..767), betas (id 768)
// ===================================================================
__global__ void prep_b(const float* __restrict__ cWq, const float* __restrict__ mWq,
                       const float* __restrict__ cWo, const float* __restrict__ mWo)
{
    const int id = blockIdx.x;
    const int tid = threadIdx.x;
    if (id < 512) {
        const int e = id;
        __shared__ float swc[512], swm[512];
        swc[tid] = cWq[e * 512 + tid];
        swm[tid] = mWq[e * 512 + tid];
        __syncthreads();
        if (tid < 256) {
            const int n = tid, g = n >> 5, t = n & 31;
            float acc = 0.f;
            if (t < 19) {
                for (int d = 0; d < 64; d++) acc += swc[g * 64 + d] * g_Kc[t * 512 + g * 64 + d];
            } else if (t < 29) {
                const int j = t - 19;
                for (int d = 0; d < 64; d++) acc += swm[g * 64 + d] * g_Km[j * 512 + g * 64 + d];
            }
            g_KQ[e * 256 + n] = acc * 0.125f;
        }
    } else if (id < 768) {
        const int n = id - 512, g = n >> 5, t = n & 31;
        __shared__ float sv[64];
        const bool pad = (t >= 29);
        const float* V; const float* Wo; int j;
        if (t < 19)      { V = g_Vc; Wo = cWo; j = t; }
        else if (t < 29) { V = g_Vm; Wo = mWo; j = t - 19; }
        else             { V = g_Vc; Wo = cWo; j = 0; }
        const int f = tid;
        if (f < 64) sv[f] = V[j * 512 + g * 64 + f];
        __syncthreads();
        float acc = 0.f;
        for (int e = 0; e < 64; e++) acc += sv[e] * Wo[(g * 64 + e) * 512 + f];
        g_VW[n * 512 + f] = pad ? 0.f : acc;
    } else if (tid < 256) {
        const int n = tid, g = n >> 5, t = n & 31;
        float b1 = 0.f, b2 = 0.f;
        if (t < 19) {
            for (int d = 0; d < 64; d++) {
                const float kk = g_Kc[t * 512 + g * 64 + d];
                b1 += g_bf1[g * 64 + d] * kk;
                b2 += g_bf2c[g * 64 + d] * kk;
            }
        } else if (t < 29) {
            const int j = t - 19;
            for (int d = 0; d < 64; d++) {
                const float kk = g_Km[j * 512 + g * 64 + d];
                b1 += g_bf1[512 + g * 64 + d] * kk;
                b2 += g_bf2m[g * 64 + d] * kk;
            }
        }
        g_beta1[n] = b1 * 0.125f;
        g_beta2[n] = b2 * 0.125f;
    }
}

// ===================================================================
// prep level C (256 threads, dynamic smem):
//   ids 0..127  : P1T[n][k0..k0+8) = W_lin @ KQ
//   ids 128..143: GT 64x64 tile = mask ∘ (VW @ KQ)^T
// ===================================================================
#define PREPC_SMEM (2 * 64 * 65 * 4)

__global__ void prep_c(const float* __restrict__ W_lin)
{
    extern __shared__ float shd[];
    const int id = blockIdx.x;
    const int tid = threadIdx.x;   // 256
    if (id < 128) {
        const int k0 = id * 8;
        float* sw = shd;           // [8][512]
        for (int i = tid; i < 8 * 512; i += 256)
            sw[i] = W_lin[(size_t)(k0 + (i >> 9)) * 512 + (i & 511)];
        __syncthreads();
        float acc[8] = {0, 0, 0, 0, 0, 0, 0, 0};
        for (int e = 0; e < 512; e++) {
            const float kq = g_KQ[e * 256 + tid];
#pragma unroll
            for (int r = 0; r < 8; r++) acc[r] += sw[r * 512 + e] * kq;
        }
#pragma unroll
        for (int r = 0; r < 8; r++)
            g_P1T[(size_t)tid * 1024 + k0 + r] = __float2bfloat16(acc[r]);
    } else {
        const int bt = id - 128;
        const int np0 = (bt & 3) * 64;
        const int no0 = (bt >> 2) * 64;
        float* As = shd;               // [64][65]
        float* Bs = shd + 64 * 65;     // [64][65]
        float accv[4][4];
#pragma unroll
        for (int i = 0; i < 4; i++)
#pragma unroll
            for (int j = 0; j < 4; j++) accv[i][j] = 0.f;

        const int tx = tid & 15, ty = tid >> 4;
        for (int k0 = 0; k0 < 512; k0 += 64) {
            for (int i = tid; i < 64 * 16; i += 256) {
                const int r = i >> 4, c4 = i & 15;
                const float4 v = *(const float4*)&g_VW[(size_t)(np0 + r) * 512 + k0 + c4 * 4];
                float* d = &As[r * 65 + c4 * 4];
                d[0] = v.x; d[1] = v.y; d[2] = v.z; d[3] = v.w;
            }
            for (int i = tid; i < 64 * 16; i += 256) {
                const int r = i >> 4, c4 = i & 15;
                const float4 v = *(const float4*)&g_KQ[(size_t)(k0 + r) * 256 + no0 + c4 * 4];
                float* d = &Bs[r * 65 + c4 * 4];
                d[0] = v.x; d[1] = v.y; d[2] = v.z; d[3] = v.w;
            }
            __syncthreads();
#pragma unroll 8
            for (int kk = 0; kk < 64; kk++) {
                float av[4], bv[4];
#pragma unroll
                for (int i = 0; i < 4; i++) av[i] = As[(ty * 4 + i) * 65 + kk];
#pragma unroll
                for (int j = 0; j < 4; j++) bv[j] = Bs[kk * 65 + tx * 4 + j];
#pragma unroll
                for (int i = 0; i < 4; i++)
#pragma unroll
                    for (int j = 0; j < 4; j++) accv[i][j] += av[i] * bv[j];
            }
            __syncthreads();
        }
#pragma unroll
        for (int i = 0; i < 4; i++) {
            const int np = np0 + ty * 4 + i, tnp = np & 31;
#pragma unroll
            for (int j = 0; j < 4; j++) {
                const int no = no0 + tx * 4 + j, tno = no & 31;
                const bool ok = (tno < 29) && (tnp < 29) && ((tno < 19) == (tnp < 19));
                g_GT[(size_t)no * 256 + np] = __float2bfloat16(ok ? accv[i][j] : 0.f);
            }
        }
    }
}

// ===================================================================
// Fused kernel: one CTA per 128-row tile, 512 threads (16 warps, 4m x 4n).
//  Pass 1: logits1 = emb(fp32->bf16) @ P1T^T, BK=64, softmax -> W1 SMEM panels.
//  Pass 2: logits2 = W1 @ GT^T (GT cp.async streamed), softmax, colsum -> part.
// SMEM: APAN=0 (2x16KB), B1S=32768 (3x32KB; GT stages 3x8KB reuse), W1P=131072 (8x8KB)
// ===================================================================
#define SMEM_FUSED (196608 + 1024)

__global__ __launch_bounds__(512, 1)
void fused_all(const float* __restrict__ Af,
               const __nv_bfloat16* __restrict__ P1T,
               const __nv_bfloat16* __restrict__ GT,
               const float* __restrict__ beta1, const float* __restrict__ beta2,
               const int* __restrict__ cmask, const int* __restrict__ mmask,
               float* __restrict__ part)
{
    extern __shared__ __align__(16) char dsm[];
    const uint32_t sbase = (smem_u32(dsm) + 1023u) & ~1023u;
    const uint32_t APAN = sbase;            // 2 x 16KB A panels (128 rows x 128B)
    const uint32_t B1S  = sbase + 32768;    // 3 x 32KB B1 stages / 3 x 8KB GT stages
    const uint32_t W1P  = sbase + 131072;   // 8 x 8KB W1 panels
    __shared__ float smk[32];
    __shared__ float spart[4][NP];

    const int tid  = threadIdx.x;
    const int warp = tid >> 5, lane = tid & 31;
    const int wm = warp >> 2;        // 0..3 -> m offset *32
    const int wn = warp & 3;         // 0..3 -> n offset *64 (pass1) / *32 (pass2)
    const int tile = blockIdx.x;
    const int m0 = tile * 128;
    const int b  = tile >> 4;
    const int lq = lane & 3;

    if (tid < 32) {
        float v;
        if (tid < 19)      v = (float)cmask[b * 19 + tid];
        else if (tid < 29) v = (float)mmask[b * 10 + tid - 19];
        else               v = -1e30f;
        smk[tid] = v;
    }

    const int a_row = lane & 15;
    const int a_k8  = (lane >> 4) << 3;
    const int b_row = (lane & 7) | ((lane >> 4) << 3);
    const int b_k8  = ((lane >> 3) & 1) << 3;

    // ================= pass 1 mainloop (BK=64, 16 iterations) =================
    float acc1[2][8][4];
#pragma unroll
    for (int i = 0; i < 2; i++)
#pragma unroll
        for (int j = 0; j < 8; j++)
#pragma unroll
            for (int r = 0; r < 4; r++) acc1[i][j][r] = 0.f;

    // A: row = tid>>2 (4 threads/row), each thread 16 fp32 at col (tid&3)*16
    const float* aptr = Af + (size_t)(m0 + (tid >> 2)) * 1024 + (tid & 3) * 16;
    float4 ar0, ar1, ar2, ar3;
    auto ldgA = [&](int kt) {
        const float4* p = (const float4*)(aptr + kt * 64);
        ar0 = p[0]; ar1 = p[1]; ar2 = p[2]; ar3 = p[3];
    };
    auto stsA = [&](int buf) {
        const uint32_t byte = (uint32_t)(tid >> 2) * 128 + (uint32_t)(tid & 3) * 32;
        const uint32_t a0 = APAN + buf * 16384 + sw128(byte);
        const uint32_t a1 = APAN + buf * 16384 + sw128(byte + 16);
        uint32_t h0 = pk2(ar0.x, ar0.y), h1 = pk2(ar0.z, ar0.w);
        uint32_t h2 = pk2(ar1.x, ar1.y), h3 = pk2(ar1.z, ar1.w);
        uint32_t h4 = pk2(ar2.x, ar2.y), h5 = pk2(ar2.z, ar2.w);
        uint32_t h6 = pk2(ar3.x, ar3.y), h7 = pk2(ar3.z, ar3.w);
        asm volatile("st.shared.v4.b32 [%0], {%1,%2,%3,%4};"
                     :: "r"(a0), "r"(h0), "r"(h1), "r"(h2), "r"(h3));
        asm volatile("st.shared.v4.b32 [%0], {%1,%2,%3,%4};"
                     :: "r"(a1), "r"(h4), "r"(h5), "r"(h6), "r"(h7));
    };
    auto loadB1 = [&](int s, int kt) {
        const uint32_t bb = B1S + s * 32768;
        const __nv_bfloat16* Bg = P1T + kt * 64;
#pragma unroll
        for (int t = 0; t < 4; t++) {
            int id  = tid + t * 512;
            int row = id >> 3, c = id & 7;   // 256 rows x 8 chunks of 16B
            uint32_t byte = row * 128 + c * 16;
            cp_async16(bb + sw128(byte), Bg + (size_t)row * 1024 + c * 8);
        }
    };

    ldgA(0);
    loadB1(0, 0);
    asm volatile("cp.async.commit_group;");
    loadB1(1, 1);
    asm volatile("cp.async.commit_group;");

    for (int kt = 0; kt < 16; kt++) {
        stsA(kt & 1);
        if (kt + 1 < 16) ldgA(kt + 1);
        asm volatile("cp.async.wait_group 1;");
        __syncthreads();
        if (kt + 2 < 16) loadB1((kt + 2) % 3, kt + 2);
        asm volatile("cp.async.commit_group;");

        const uint32_t aS = APAN + (kt & 1) * 16384;
        const uint32_t bS = B1S + (kt % 3) * 32768;
#pragma unroll
        for (int kk = 0; kk < 4; kk++) {
            uint32_t a[2][4], bfr[4][4];
#pragma unroll
            for (int mt = 0; mt < 2; mt++) {
                uint32_t byte = (uint32_t)(wm * 32 + mt * 16 + a_row) * 128
                              + (uint32_t)(kk * 16 + a_k8) * 2;
                uint32_t ad = aS + sw128(byte);
                asm volatile(
                    "ldmatrix.sync.aligned.m8n8.x4.shared.b16 {%0,%1,%2,%3}, [%4];"
                    : "=r"(a[mt][0]), "=r"(a[mt][1]), "=r"(a[mt][2]), "=r"(a[mt][3])
                    : "r"(ad));
            }
#pragma unroll
            for (int np = 0; np < 4; np++) {
                uint32_t byte = (uint32_t)(wn * 64 + np * 16 + b_row) * 128
                              + (uint32_t)(kk * 16 + b_k8) * 2;
                uint32_t bd = bS + sw128(byte);
                asm volatile(
                    "ldmatrix.sync.aligned.m8n8.x4.shared.b16 {%0,%1,%2,%3}, [%4];"
                    : "=r"(bfr[np][0]), "=r"(bfr[np][1]), "=r"(bfr[np][2]), "=r"(bfr[np][3])
                    : "r"(bd));
            }
#pragma unroll
            for (int mt = 0; mt < 2; mt++)
#pragma unroll
                for (int nt = 0; nt < 8; nt++) {
                    const uint32_t b0 = bfr[nt >> 1][(nt & 1) * 2];
                    const uint32_t b1v = bfr[nt >> 1][(nt & 1) * 2 + 1];
                    asm volatile(
                        "mma.sync.aligned.m16n8k16.row.col.f32.bf16.bf16.f32 "
                        "{%0,%1,%2,%3}, {%4,%5,%6,%7}, {%8,%9}, {%0,%1,%2,%3};"
                        : "+f"(acc1[mt][nt][0]), "+f"(acc1[mt][nt][1]),
                          "+f"(acc1[mt][nt][2]), "+f"(acc1[mt][nt][3])
                        : "r"(a[mt][0]), "r"(a[mt][1]), "r"(a[mt][2]), "r"(a[mt][3]),
                          "r"(b0), "r"(b1v));
                }
        }
        __syncthreads();
    }

    // ---- prefetch GT stages 0,1 (reuse B1 region) ----
    auto loadGT = [&](int s, int gidx) {
        const int h2 = gidx >> 3, k2 = gidx & 7;
        const uint32_t bb = B1S + s * 8192;
        const int row = tid >> 2, c = tid & 3;
        uint32_t byte = row * 64 + c * 16;
        cp_async16(bb + sw128(byte), GT + (size_t)(h2 * 128 + row) * 256 + k2 * 32 + c * 8);
    };
    loadGT(0, 0);
    asm volatile("cp.async.commit_group;");
    loadGT(1, 1);
    asm volatile("cp.async.commit_group;");

    // ================= pass-1 epilogue: softmax -> W1 panels =================
#pragma unroll
    for (int gh = 0; gh < 2; gh++) {
        const int g = wn * 2 + gh;
        float addv[4][2]; bool isc[4][2];
#pragma unroll
        for (int nt = 0; nt < 4; nt++)
#pragma unroll
            for (int q = 0; q < 2; q++) {
                const int t = nt * 8 + lq * 2 + q;
                addv[nt][q] = beta1[g * 32 + t] + smk[t];
                isc[nt][q]  = (t < 19);
            }
#pragma unroll
        for (int mt = 0; mt < 2; mt++) {
#pragma unroll
            for (int rr = 0; rr < 2; rr++) {
                float v[4][2];
                float mc = -1e30f, mmx = -1e30f;
#pragma unroll
                for (int nt = 0; nt < 4; nt++)
#pragma unroll
                    for (int q = 0; q < 2; q++) {
                        v[nt][q] = acc1[mt][gh * 4 + nt][rr * 2 + q] + addv[nt][q];
                        if (isc[nt][q]) mc = fmaxf(mc, v[nt][q]);
                        else            mmx = fmaxf(mmx, v[nt][q]);
                    }
                mc  = fmaxf(mc,  __shfl_xor_sync(0xffffffffu, mc, 1));
                mc  = fmaxf(mc,  __shfl_xor_sync(0xffffffffu, mc, 2));
                mmx = fmaxf(mmx, __shfl_xor_sync(0xffffffffu, mmx, 1));
                mmx = fmaxf(mmx, __shfl_xor_sync(0xffffffffu, mmx, 2));

                float e[4][2];
                float sc = 0.f, sm = 0.f;
#pragma unroll
                for (int nt = 0; nt < 4; nt++)
#pragma unroll
                    for (int q = 0; q < 2; q++) {
                        const float ev = __expf(v[nt][q] - (isc[nt][q] ? mc : mmx));
                        e[nt][q] = ev;
                        if (isc[nt][q]) sc += ev; else sm += ev;
                    }
                sc += __shfl_xor_sync(0xffffffffu, sc, 1);
                sc += __shfl_xor_sync(0xffffffffu, sc, 2);
                sm += __shfl_xor_sync(0xffffffffu, sm, 1);
                sm += __shfl_xor_sync(0xffffffffu, sm, 2);
                const float ic = 1.f / sc, im = 1.f / sm;

                const int r_loc = wm * 32 + mt * 16 + (lane >> 2) + rr * 8;
                const uint32_t pbase = W1P + g * 8192;
#pragma unroll
                for (int nt = 0; nt < 4; nt++) {
                    const float w0 = e[nt][0] * (isc[nt][0] ? ic : im);
                    const float w1 = e[nt][1] * (isc[nt][1] ? ic : im);
                    const uint32_t byte = (uint32_t)r_loc * 64 + (uint32_t)(nt * 8 + lq * 2) * 2;
                    const uint32_t hh = pk2(w0, w1);
                    asm volatile("st.shared.b32 [%0], %1;"
                                 :: "r"(pbase + sw128(byte)), "r"(hh));
                }
            }
        }
    }
    __syncthreads();

    // ================= pass 2: W1 @ GT^T, two N-halves =================
#pragma unroll 1
    for (int h = 0; h < 2; h++) {
        float acc2[2][4][4];
#pragma unroll
        for (int i = 0; i < 2; i++)
#pragma unroll
            for (int j = 0; j < 4; j++)
#pragma unroll
                for (int r = 0; r < 4; r++) acc2[i][j][r] = 0.f;

#pragma unroll 1
        for (int k2 = 0; k2 < 8; k2++) {
            const int gidx = h * 8 + k2;
            asm volatile("cp.async.wait_group 1;");
            __syncthreads();
            if (gidx + 2 < 16) loadGT((gidx + 2) % 3, gidx + 2);
            asm volatile("cp.async.commit_group;");

            const uint32_t aS = W1P + k2 * 8192;
            const uint32_t bS = B1S + (gidx % 3) * 8192;
#pragma unroll
            for (int kk = 0; kk < 2; kk++) {
                uint32_t a[2][4], bfr[2][4];
#pragma unroll
                for (int mt = 0; mt < 2; mt++) {
                    uint32_t byte = (uint32_t)(wm * 32 + mt * 16 + a_row) * 64
                                  + (uint32_t)(kk * 16 + a_k8) * 2;
                    uint32_t ad = aS + sw128(byte);
                    asm volatile(
                        "ldmatrix.sync.aligned.m8n8.x4.shared.b16 {%0,%1,%2,%3}, [%4];"
                        : "=r"(a[mt][0]), "=r"(a[mt][1]), "=r"(a[mt][2]), "=r"(a[mt][3])
                        : "r"(ad));
                }
#pragma unroll
                for (int np = 0; np < 2; np++) {
                    uint32_t byte = (uint32_t)(wn * 32 + np * 16 + b_row) * 64
                                  + (uint32_t)(kk * 16 + b_k8) * 2;
                    uint32_t bd = bS + sw128(byte);
                    asm volatile(
                        "ldmatrix.sync.aligned.m8n8.x4.shared.b16 {%0,%1,%2,%3}, [%4];"
                        : "=r"(bfr[np][0]), "=r"(bfr[np][1]), "=r"(bfr[np][2]), "=r"(bfr[np][3])
                        : "r"(bd));
                }
#pragma unroll
                for (int mt = 0; mt < 2; mt++)
#pragma unroll
                    for (int nt = 0; nt < 4; nt++) {
                        const uint32_t b0 = bfr[nt >> 1][(nt & 1) * 2];
                        const uint32_t b1v = bfr[nt >> 1][(nt & 1) * 2 + 1];
                        asm volatile(
                            "mma.sync.aligned.m16n8k16.row.col.f32.bf16.bf16.f32 "
                            "{%0,%1,%2,%3}, {%4,%5,%6,%7}, {%8,%9}, {%0,%1,%2,%3};"
                            : "+f"(acc2[mt][nt][0]), "+f"(acc2[mt][nt][1]),
                              "+f"(acc2[mt][nt][2]), "+f"(acc2[mt][nt][3])
                            : "r"(a[mt][0]), "r"(a[mt][1]), "r"(a[mt][2]), "r"(a[mt][3]),
                              "r"(b0), "r"(b1v));
                    }
            }
            __syncthreads();
        }

        // ---- epilogue half h: softmax2 + column accumulation ----
        float addv[4][2]; bool isc[4][2];
#pragma unroll
        for (int nt = 0; nt < 4; nt++)
#pragma unroll
            for (int q = 0; q < 2; q++) {
                const int t = nt * 8 + lq * 2 + q;
                addv[nt][q] = beta2[h * 128 + wn * 32 + t] + smk[t];
                isc[nt][q]  = (t < 19);
            }
        float colacc[4][2];
#pragma unroll
        for (int nt = 0; nt < 4; nt++) { colacc[nt][0] = 0.f; colacc[nt][1] = 0.f; }

#pragma unroll
        for (int mt = 0; mt < 2; mt++) {
#pragma unroll
            for (int rr = 0; rr < 2; rr++) {
                float v[4][2];
                float mc = -1e30f, mmx = -1e30f;
#pragma unroll
                for (int nt = 0; nt < 4; nt++)
#pragma unroll
                    for (int q = 0; q < 2; q++) {
                        v[nt][q] = acc2[mt][nt][rr * 2 + q] + addv[nt][q];
                        if (isc[nt][q]) mc = fmaxf(mc, v[nt][q]);
                        else            mmx = fmaxf(mmx, v[nt][q]);
                    }
                mc  = fmaxf(mc,  __shfl_xor_sync(0xffffffffu, mc, 1));
                mc  = fmaxf(mc,  __shfl_xor_sync(0xffffffffu, mc, 2));
                mmx = fmaxf(mmx, __shfl_xor_sync(0xffffffffu, mmx, 1));
                mmx = fmaxf(mmx, __shfl_xor_sync(0xffffffffu, mmx, 2));

                float e[4][2];
                float sc = 0.f, sm = 0.f;
#pragma unroll
                for (int nt = 0; nt < 4; nt++)
#pragma unroll
                    for (int q = 0; q < 2; q++) {
                        const float ev = __expf(v[nt][q] - (isc[nt][q] ? mc : mmx));
                        e[nt][q] = ev;
                        if (isc[nt][q]) sc += ev; else sm += ev;
                    }
                sc += __shfl_xor_sync(0xffffffffu, sc, 1);
                sc += __shfl_xor_sync(0xffffffffu, sc, 2);
                sm += __shfl_xor_sync(0xffffffffu, sm, 1);
                sm += __shfl_xor_sync(0xffffffffu, sm, 2);
                const float ic = 1.f / sc, im = 1.f / sm;
#pragma unroll
                for (int nt = 0; nt < 4; nt++)
#pragma unroll
                    for (int q = 0; q < 2; q++)
                        colacc[nt][q] += e[nt][q] * (isc[nt][q] ? ic : im);
            }
        }
#pragma unroll
        for (int st = 4; st < 32; st <<= 1)
#pragma unroll
            for (int nt = 0; nt < 4; nt++) {
                colacc[nt][0] += __shfl_xor_sync(0xffffffffu, colacc[nt][0], st);
                colacc[nt][1] += __shfl_xor_sync(0xffffffffu, colacc[nt][1], st);
            }
        if (lane < 4) {
#pragma unroll
            for (int nt = 0; nt < 4; nt++) {
                spart[wm][h * 128 + wn * 32 + nt * 8 + lane * 2]     = colacc[nt][0];
                spart[wm][h * 128 + wn * 32 + nt * 8 + lane * 2 + 1] = colacc[nt][1];
            }
        }
    }

    __syncthreads();
    if (tid < NP)
        part[(size_t)tile * NP + tid] =
            spart[0][tid] + spart[1][tid] + spart[2][tid] + spart[3][tid];
}

// ===================================================================
// final: Wsum = sum of 16 tile parts; out = Wsum . VWo / pmsum + S*bo/pmsum
// ===================================================================
__global__ void final_kernel(const float* __restrict__ cbo, const float* __restrict__ mbo,
                             float* __restrict__ out)
{
    __shared__ float ws[NP];
    const int b = blockIdx.x, tid = threadIdx.x;
    if (tid < NP) {
        float s = 0.f;
#pragma unroll
        for (int p = 0; p < 16; p++) s += g_part[(size_t)(b * 16 + p) * NP + tid];
        ws[tid] = s;
    }
    __syncthreads();
    const int c = tid;   // 512 threads
    float oc = 0.f, om = 0.f;
#pragma unroll 1
    for (int g = 0; g < 8; g++) {
#pragma unroll
        for (int t = 0; t < 19; t++) oc += ws[g * 32 + t] * g_VW[(size_t)(g * 32 + t) * 512 + c];
#pragma unroll
        for (int t = 19; t < 29; t++) om += ws[g * 32 + t] * g_VW[(size_t)(g * 32 + t) * 512 + c];
    }
    const float invp = 1.f / g_pmsum[b];
    oc = (oc + 2048.f * cbo[c]) * invp;
    om = (om + 2048.f * mbo[c]) * invp;
    out[b * 512 + c] = oc;
    out[BATCH * 512 + b * 512 + c] = oc - om;
}

// ===================================================================
extern "C" void kernel_launch(void* const* d_in, const int* in_sizes, int n_in,
                              void* d_out, int out_size)
{
    const float* emb   = (const float*)d_in[0];
    const int*   emask = (const int*)d_in[1];
    const int*   pmask = (const int*)d_in[2];
    // d_in[3] frame_mask cancels in softmax — unused
    const int*   cmask = (const int*)d_in[4];
    const int*   mmask = (const int*)d_in[5];
    const float* W_lin = (const float*)d_in[6];
    const float* b_lin = (const float*)d_in[7];
    const float* ctab  = (const float*)d_in[8];
    const float* mtab  = (const float*)d_in[9];
    const float* cWq = (const float*)d_in[10]; const float* cbq = (const float*)d_in[11];
    const float* cWk = (const float*)d_in[12]; const float* cbk = (const float*)d_in[13];
    const float* cWv = (const float*)d_in[14]; const float* cbv = (const float*)d_in[15];
    const float* cWo = (const float*)d_in[16]; const float* cbo = (const float*)d_in[17];
    const float* mWq = (const float*)d_in[18]; const float* mbq = (const float*)d_in[19];
    const float* mWk = (const float*)d_in[20]; const float* mbk = (const float*)d_in[21];
    const float* mWv = (const float*)d_in[22]; const float* mbv = (const float*)d_in[23];
    const float* mWo = (const float*)d_in[24]; const float* mbo = (const float*)d_in[25];
    float* out = (float*)d_out;

    __nv_bfloat16 *pP1T, *pGT;
    float *pbeta1, *pbeta2, *pPart;
    cudaGetSymbolAddress((void**)&pP1T,   g_P1T);
    cudaGetSymbolAddress((void**)&pGT,    g_GT);
    cudaGetSymbolAddress((void**)&pbeta1, g_beta1);
    cudaGetSymbolAddress((void**)&pbeta2, g_beta2);
    cudaGetSymbolAddress((void**)&pPart,  g_part);

    cudaFuncSetAttribute((const void*)fused_all,
                         cudaFuncAttributeMaxDynamicSharedMemorySize, SMEM_FUSED);

    // prep chain (3 launches, by dependency level)
    prep_ab<<<94, 512>>>(ctab, mtab, cWk, cbk, cWv, cbv, mWk, mbk, mWv, mbv,
                         b_lin, cWq, cbq, mWq, mbq, cbo, mbo, emask, pmask);
    prep_b<<<769, 512>>>(cWq, mWq, cWo, mWo);
    prep_c<<<144, 256, PREPC_SMEM>>>(W_lin);

    // fused pass 1 + pass 2
    fused_all<<<512, 512, SMEM_FUSED>>>(emb, pP1T, pGT, pbeta1, pbeta2,
                                        cmask, mmask, pPart);

    final_kernel<<<BATCH, 512>>>(cbo, mbo, out);
}

// round 10
// speedup vs baseline: 1.2536x; 1.2536x over previous
#include <cuda_runtime.h>
#include <cuda_bf16.h>
#include <cstdint>

// ---------------- problem constants ----------------
#define BATCH 32
#define SEQ   2048
#define NROWS (BATCH*SEQ)   // 65536
#define NP 256              // packed columns: 8 head-groups x (19 cult | 10 moral | 3 pad)

// ---------------- scratch (device globals) ----------------
__device__ __nv_bfloat16 g_P1T[NP*1024];               // B of pass 1: [n][k]
__device__ __nv_bfloat16 g_GT[NP*NP];                  // B of pass 2: GT[n_out][n_in]
__device__ float g_KQ[512*NP];                         // KQ[e][n] (includes 1/8)
__device__ float g_VW[NP*512];                         // VWo[n][f]
__device__ float g_beta1[NP], g_beta2[NP];
__device__ float g_Kc[19*512], g_Vc[19*512], g_Km[10*512], g_Vm[10*512];
__device__ float g_bf1[1024];
__device__ float g_bf2c[512], g_bf2m[512];
__device__ float g_pmsum[BATCH];
__device__ float g_part[1024*NP];

__device__ __forceinline__ uint32_t smem_u32(const void* p) {
    return (uint32_t)__cvta_generic_to_shared(p);
}
__device__ __forceinline__ void cp_async16(uint32_t dst, const void* src) {
    asm volatile("cp.async.cg.shared.global [%0], [%1], 16;" :: "r"(dst), "l"(src));
}
__device__ __forceinline__ uint32_t sw128(uint32_t b) { return b ^ ((b >> 3) & 0x70u); }
__device__ __forceinline__ uint32_t pk2(float x, float y) {
    __nv_bfloat162 h = __floats2bfloat162_rn(x, y);
    return *reinterpret_cast<uint32_t*>(&h);
}

// ===================================================================
// prep level A: K/V head tables + folded bias rows + pmsum
// ===================================================================
__global__ void prep_ab(const float* __restrict__ ctab, const float* __restrict__ mtab,
                        const float* __restrict__ cWk, const float* __restrict__ cbk,
                        const float* __restrict__ cWv, const float* __restrict__ cbv,
                        const float* __restrict__ mWk, const float* __restrict__ mbk,
                        const float* __restrict__ mWv, const float* __restrict__ mbv,
                        const float* __restrict__ b_lin,
                        const float* __restrict__ cWq, const float* __restrict__ cbq,
                        const float* __restrict__ mWq, const float* __restrict__ mbq,
                        const float* __restrict__ cbo, const float* __restrict__ mbo,
                        const int* __restrict__ em, const int* __restrict__ pmask)
{
    const int id = blockIdx.x;
    const int tid = threadIdx.x;
    if (id < 62) {
        const float* arow; const float* W; const float* bb; float* out;
        if      (id < 19)  { arow = ctab + id * 512;        W = cWk; bb = cbk; out = g_Kc + id * 512; }
        else if (id < 38)  { arow = ctab + (id - 19) * 512; W = cWv; bb = cbv; out = g_Vc + (id - 19) * 512; }
        else if (id < 48)  { arow = mtab + (id - 38) * 512; W = mWk; bb = mbk; out = g_Km + (id - 38) * 512; }
        else if (id < 58)  { arow = mtab + (id - 48) * 512; W = mWv; bb = mbv; out = g_Vm + (id - 48) * 512; }
        else if (id == 58) { arow = b_lin; W = cWq; bb = cbq; out = g_bf1; }
        else if (id == 59) { arow = b_lin; W = mWq; bb = mbq; out = g_bf1 + 512; }
        else if (id == 60) { arow = cbo;   W = cWq; bb = cbq; out = g_bf2c; }
        else               { arow = mbo;   W = mWq; bb = mbq; out = g_bf2m; }

        __shared__ float sA[512];
        sA[tid] = arow[tid];
        __syncthreads();
        float acc = bb[tid];
        for (int k = 0; k < 512; k++) acc += sA[k] * W[k * 512 + tid];
        out[tid] = acc;
    } else {
        const int b = id - 62;
        __shared__ int sred[16];
        int cnt = 0;
        for (int s = tid; s < SEQ; s += 512) cnt += em[b * SEQ + s] * pmask[b * SEQ + s];
#pragma unroll
        for (int st = 16; st; st >>= 1) cnt += __shfl_xor_sync(0xffffffffu, cnt, st);
        if ((tid & 31) == 0) sred[tid >> 5] = cnt;
        __syncthreads();
        if (tid == 0) {
            int tot = 0;
            for (int w = 0; w < 16; w++) tot += sred[w];
            g_pmsum[b] = (float)tot;
        }
    }
}

// ===================================================================
// prep level B: kq (ids 0..511), vwo (ids 512..767), betas (id 768)
// ===================================================================
__global__ void prep_b(const float* __restrict__ cWq, const float* __restrict__ mWq,
                       const float* __restrict__ cWo, const float* __restrict__ mWo)
{
    const int id = blockIdx.x;
    const int tid = threadIdx.x;
    if (id < 512) {
        const int e = id;
        __shared__ float swc[512], swm[512];
        swc[tid] = cWq[e * 512 + tid];
        swm[tid] = mWq[e * 512 + tid];
        __syncthreads();
        if (tid < 256) {
            const int n = tid, g = n >> 5, t = n & 31;
            float acc = 0.f;
            if (t < 19) {
                for (int d = 0; d < 64; d++) acc += swc[g * 64 + d] * g_Kc[t * 512 + g * 64 + d];
            } else if (t < 29) {
                const int j = t - 19;
                for (int d = 0; d < 64; d++) acc += swm[g * 64 + d] * g_Km[j * 512 + g * 64 + d];
            }
            g_KQ[e * 256 + n] = acc * 0.125f;
        }
    } else if (id < 768) {
        const int n = id - 512, g = n >> 5, t = n & 31;
        __shared__ float sv[64];
        const bool pad = (t >= 29);
        const float* V; const float* Wo; int j;
        if (t < 19)      { V = g_Vc; Wo = cWo; j = t; }
        else if (t < 29) { V = g_Vm; Wo = mWo; j = t - 19; }
        else             { V = g_Vc; Wo = cWo; j = 0; }
        const int f = tid;
        if (f < 64) sv[f] = V[j * 512 + g * 64 + f];
        __syncthreads();
        float acc = 0.f;
        for (int e = 0; e < 64; e++) acc += sv[e] * Wo[(g * 64 + e) * 512 + f];
        g_VW[n * 512 + f] = pad ? 0.f : acc;
    } else if (tid < 256) {
        const int n = tid, g = n >> 5, t = n & 31;
        float b1 = 0.f, b2 = 0.f;
        if (t < 19) {
            for (int d = 0; d < 64; d++) {
                const float kk = g_Kc[t * 512 + g * 64 + d];
                b1 += g_bf1[g * 64 + d] * kk;
                b2 += g_bf2c[g * 64 + d] * kk;
            }
        } else if (t < 29) {
            const int j = t - 19;
            for (int d = 0; d < 64; d++) {
                const float kk = g_Km[j * 512 + g * 64 + d];
                b1 += g_bf1[512 + g * 64 + d] * kk;
                b2 += g_bf2m[g * 64 + d] * kk;
            }
        }
        g_beta1[n] = b1 * 0.125f;
        g_beta2[n] = b2 * 0.125f;
    }
}

// ===================================================================
// prep level C (256 threads, dynamic smem):
//   ids 0..127  : P1T[n][k0..k0+8) = W_lin @ KQ
//   ids 128..143: GT 64x64 tile = mask ∘ (VW @ KQ)^T
// ===================================================================
#define PREPC_SMEM (2 * 64 * 65 * 4)

__global__ void prep_c(const float* __restrict__ W_lin)
{
    extern __shared__ float shd[];
    const int id = blockIdx.x;
    const int tid = threadIdx.x;   // 256
    if (id < 128) {
        const int k0 = id * 8;
        float* sw = shd;           // [8][512]
        for (int i = tid; i < 8 * 512; i += 256)
            sw[i] = W_lin[(size_t)(k0 + (i >> 9)) * 512 + (i & 511)];
        __syncthreads();
        float acc[8] = {0, 0, 0, 0, 0, 0, 0, 0};
        for (int e = 0; e < 512; e++) {
            const float kq = g_KQ[e * 256 + tid];
#pragma unroll
            for (int r = 0; r < 8; r++) acc[r] += sw[r * 512 + e] * kq;
        }
#pragma unroll
        for (int r = 0; r < 8; r++)
            g_P1T[(size_t)tid * 1024 + k0 + r] = __float2bfloat16(acc[r]);
    } else {
        const int bt = id - 128;
        const int np0 = (bt & 3) * 64;
        const int no0 = (bt >> 2) * 64;
        float* As = shd;               // [64][65]
        float* Bs = shd + 64 * 65;     // [64][65]
        float accv[4][4];
#pragma unroll
        for (int i = 0; i < 4; i++)
#pragma unroll
            for (int j = 0; j < 4; j++) accv[i][j] = 0.f;

        const int tx = tid & 15, ty = tid >> 4;
        for (int k0 = 0; k0 < 512; k0 += 64) {
            for (int i = tid; i < 64 * 16; i += 256) {
                const int r = i >> 4, c4 = i & 15;
                const float4 v = *(const float4*)&g_VW[(size_t)(np0 + r) * 512 + k0 + c4 * 4];
                float* d = &As[r * 65 + c4 * 4];
                d[0] = v.x; d[1] = v.y; d[2] = v.z; d[3] = v.w;
            }
            for (int i = tid; i < 64 * 16; i += 256) {
                const int r = i >> 4, c4 = i & 15;
                const float4 v = *(const float4*)&g_KQ[(size_t)(k0 + r) * 256 + no0 + c4 * 4];
                float* d = &Bs[r * 65 + c4 * 4];
                d[0] = v.x; d[1] = v.y; d[2] = v.z; d[3] = v.w;
            }
            __syncthreads();
#pragma unroll 8
            for (int kk = 0; kk < 64; kk++) {
                float av[4], bv[4];
#pragma unroll
                for (int i = 0; i < 4; i++) av[i] = As[(ty * 4 + i) * 65 + kk];
#pragma unroll
                for (int j = 0; j < 4; j++) bv[j] = Bs[kk * 65 + tx * 4 + j];
#pragma unroll
                for (int i = 0; i < 4; i++)
#pragma unroll
                    for (int j = 0; j < 4; j++) accv[i][j] += av[i] * bv[j];
            }
            __syncthreads();
        }
#pragma unroll
        for (int i = 0; i < 4; i++) {
            const int np = np0 + ty * 4 + i, tnp = np & 31;
#pragma unroll
            for (int j = 0; j < 4; j++) {
                const int no = no0 + tx * 4 + j, tno = no & 31;
                const bool ok = (tno < 29) && (tnp < 29) && ((tno < 19) == (tnp < 19));
                g_GT[(size_t)no * 256 + np] = __float2bfloat16(ok ? accv[i][j] : 0.f);
            }
        }
    }
}

// ===================================================================
// Fused kernel: one CTA per 64-row tile, 256 threads (8 warps, 2m x 4n),
// TWO CTAs per SM (88KB smem each).
//  Pass 1: logits1 = emb(fp32->bf16) @ P1T^T, BK=32, softmax -> W1 SMEM panels.
//  Pass 2: logits2 = W1 @ GT^T (GT cp.async streamed), softmax, colsum -> part.
// SMEM: APAN=0 (2x4KB), B1S=8192 (3x16KB; GT stages 3x8KB reuse), W1P=57344 (8x4KB)
// ===================================================================
#define SMEM_FUSED (90112 + 1024)

__global__ __launch_bounds__(256, 2)
void fused_all(const float* __restrict__ Af,
               const __nv_bfloat16* __restrict__ P1T,
               const __nv_bfloat16* __restrict__ GT,
               const float* __restrict__ beta1, const float* __restrict__ beta2,
               const int* __restrict__ cmask, const int* __restrict__ mmask,
               float* __restrict__ part)
{
    extern __shared__ __align__(16) char dsm[];
    const uint32_t sbase = (smem_u32(dsm) + 1023u) & ~1023u;
    const uint32_t APAN = sbase;            // 2 x 4KB A panels (64 rows x 64B)
    const uint32_t B1S  = sbase + 8192;     // 3 x 16KB B1 stages / 3 x 8KB GT stages
    const uint32_t W1P  = sbase + 57344;    // 8 x 4KB W1 panels
    __shared__ float smk[32];
    __shared__ float spart[2][NP];

    const int tid  = threadIdx.x;
    const int warp = tid >> 5, lane = tid & 31;
    const int wm = warp >> 2;        // 0..1 -> m offset *32
    const int wn = warp & 3;         // 0..3 -> n offset *64 (pass1) / *32 (pass2)
    const int tile = blockIdx.x;     // 1024 tiles of 64 rows
    const int m0 = tile * 64;
    const int b  = tile >> 5;
    const int lq = lane & 3;

    if (tid < 32) {
        float v;
        if (tid < 19)      v = (float)cmask[b * 19 + tid];
        else if (tid < 29) v = (float)mmask[b * 10 + tid - 19];
        else               v = -1e30f;
        smk[tid] = v;
    }

    const int a_row = lane & 15;
    const int a_k8  = (lane >> 4) << 3;
    const int b_row = (lane & 7) | ((lane >> 4) << 3);
    const int b_k8  = ((lane >> 3) & 1) << 3;

    // ================= pass 1 mainloop (BK=32, 32 iterations) =================
    float acc1[2][8][4];
#pragma unroll
    for (int i = 0; i < 2; i++)
#pragma unroll
        for (int j = 0; j < 8; j++)
#pragma unroll
            for (int r = 0; r < 4; r++) acc1[i][j][r] = 0.f;

    // A: row = tid>>2 (64 rows), each thread 8 fp32 at col (tid&3)*8
    const float* aptr = Af + (size_t)(m0 + (tid >> 2)) * 1024 + (tid & 3) * 8;
    float4 ar0, ar1;
    auto ldgA = [&](int kt) {
        const float4* p = (const float4*)(aptr + kt * 32);
        ar0 = p[0]; ar1 = p[1];
    };
    auto stsA = [&](int buf) {
        const uint32_t byte = (uint32_t)(tid >> 2) * 64 + (uint32_t)(tid & 3) * 16;
        const uint32_t a0 = APAN + buf * 4096 + sw128(byte);
        uint32_t h0 = pk2(ar0.x, ar0.y), h1 = pk2(ar0.z, ar0.w);
        uint32_t h2 = pk2(ar1.x, ar1.y), h3 = pk2(ar1.z, ar1.w);
        asm volatile("st.shared.v4.b32 [%0], {%1,%2,%3,%4};"
                     :: "r"(a0), "r"(h0), "r"(h1), "r"(h2), "r"(h3));
    };
    auto loadB1 = [&](int s, int kt) {
        const uint32_t bb = B1S + s * 16384;
        const __nv_bfloat16* Bg = P1T + kt * 32;
#pragma unroll
        for (int t = 0; t < 4; t++) {
            int id  = tid + t * 256;
            int row = id >> 2, c = id & 3;   // 256 rows x 4 chunks of 16B
            uint32_t byte = row * 64 + c * 16;
            cp_async16(bb + sw128(byte), Bg + (size_t)row * 1024 + c * 8);
        }
    };

    ldgA(0);
    loadB1(0, 0);
    asm volatile("cp.async.commit_group;");
    loadB1(1, 1);
    asm volatile("cp.async.commit_group;");

    for (int kt = 0; kt < 32; kt++) {
        stsA(kt & 1);
        if (kt + 1 < 32) ldgA(kt + 1);
        asm volatile("cp.async.wait_group 1;");
        __syncthreads();
        if (kt + 2 < 32) loadB1((kt + 2) % 3, kt + 2);
        asm volatile("cp.async.commit_group;");

        const uint32_t aS = APAN + (kt & 1) * 4096;
        const uint32_t bS = B1S + (kt % 3) * 16384;
#pragma unroll
        for (int kk = 0; kk < 2; kk++) {
            uint32_t a[2][4], bfr[4][4];
#pragma unroll
            for (int mt = 0; mt < 2; mt++) {
                uint32_t byte = (uint32_t)(wm * 32 + mt * 16 + a_row) * 64
                              + (uint32_t)(kk * 16 + a_k8) * 2;
                uint32_t ad = aS + sw128(byte);
                asm volatile(
                    "ldmatrix.sync.aligned.m8n8.x4.shared.b16 {%0,%1,%2,%3}, [%4];"
                    : "=r"(a[mt][0]), "=r"(a[mt][1]), "=r"(a[mt][2]), "=r"(a[mt][3])
                    : "r"(ad));
            }
#pragma unroll
            for (int np = 0; np < 4; np++) {
                uint32_t byte = (uint32_t)(wn * 64 + np * 16 + b_row) * 64
                              + (uint32_t)(kk * 16 + b_k8) * 2;
                uint32_t bd = bS + sw128(byte);
                asm volatile(
                    "ldmatrix.sync.aligned.m8n8.x4.shared.b16 {%0,%1,%2,%3}, [%4];"
                    : "=r"(bfr[np][0]), "=r"(bfr[np][1]), "=r"(bfr[np][2]), "=r"(bfr[np][3])
                    : "r"(bd));
            }
#pragma unroll
            for (int mt = 0; mt < 2; mt++)
#pragma unroll
                for (int nt = 0; nt < 8; nt++) {
                    const uint32_t b0 = bfr[nt >> 1][(nt & 1) * 2];
                    const uint32_t b1v = bfr[nt >> 1][(nt & 1) * 2 + 1];
                    asm volatile(
                        "mma.sync.aligned.m16n8k16.row.col.f32.bf16.bf16.f32 "
                        "{%0,%1,%2,%3}, {%4,%5,%6,%7}, {%8,%9}, {%0,%1,%2,%3};"
                        : "+f"(acc1[mt][nt][0]), "+f"(acc1[mt][nt][1]),
                          "+f"(acc1[mt][nt][2]), "+f"(acc1[mt][nt][3])
                        : "r"(a[mt][0]), "r"(a[mt][1]), "r"(a[mt][2]), "r"(a[mt][3]),
                          "r"(b0), "r"(b1v));
                }
        }
        __syncthreads();
    }

    // ---- prefetch GT stages 0,1 (reuse B1 region) ----
    auto loadGT = [&](int s, int gidx) {
        const int h2 = gidx >> 3, k2 = gidx & 7;
        const uint32_t bb = B1S + s * 8192;
#pragma unroll
        for (int t = 0; t < 2; t++) {
            int id = tid + t * 256;
            int row = id >> 2, c = id & 3;   // 128 rows x 4 chunks
            uint32_t byte = row * 64 + c * 16;
            cp_async16(bb + sw128(byte), GT + (size_t)(h2 * 128 + row) * 256 + k2 * 32 + c * 8);
        }
    };
    loadGT(0, 0);
    asm volatile("cp.async.commit_group;");
    loadGT(1, 1);
    asm volatile("cp.async.commit_group;");

    // ================= pass-1 epilogue: softmax -> W1 panels =================
#pragma unroll
    for (int gh = 0; gh < 2; gh++) {
        const int g = wn * 2 + gh;
        float addv[4][2]; bool isc[4][2];
#pragma unroll
        for (int nt = 0; nt < 4; nt++)
#pragma unroll
            for (int q = 0; q < 2; q++) {
                const int t = nt * 8 + lq * 2 + q;
                addv[nt][q] = beta1[g * 32 + t] + smk[t];
                isc[nt][q]  = (t < 19);
            }
#pragma unroll
        for (int mt = 0; mt < 2; mt++) {
#pragma unroll
            for (int rr = 0; rr < 2; rr++) {
                float v[4][2];
                float mc = -1e30f, mmx = -1e30f;
#pragma unroll
                for (int nt = 0; nt < 4; nt++)
#pragma unroll
                    for (int q = 0; q < 2; q++) {
                        v[nt][q] = acc1[mt][gh * 4 + nt][rr * 2 + q] + addv[nt][q];
                        if (isc[nt][q]) mc = fmaxf(mc, v[nt][q]);
                        else            mmx = fmaxf(mmx, v[nt][q]);
                    }
                mc  = fmaxf(mc,  __shfl_xor_sync(0xffffffffu, mc, 1));
                mc  = fmaxf(mc,  __shfl_xor_sync(0xffffffffu, mc, 2));
                mmx = fmaxf(mmx, __shfl_xor_sync(0xffffffffu, mmx, 1));
                mmx = fmaxf(mmx, __shfl_xor_sync(0xffffffffu, mmx, 2));

                float e[4][2];
                float sc = 0.f, sm = 0.f;
#pragma unroll
                for (int nt = 0; nt < 4; nt++)
#pragma unroll
                    for (int q = 0; q < 2; q++) {
                        const float ev = __expf(v[nt][q] - (isc[nt][q] ? mc : mmx));
                        e[nt][q] = ev;
                        if (isc[nt][q]) sc += ev; else sm += ev;
                    }
                sc += __shfl_xor_sync(0xffffffffu, sc, 1);
                sc += __shfl_xor_sync(0xffffffffu, sc, 2);
                sm += __shfl_xor_sync(0xffffffffu, sm, 1);
                sm += __shfl_xor_sync(0xffffffffu, sm, 2);
                const float ic = 1.f / sc, im = 1.f / sm;

                const int r_loc = wm * 32 + mt * 16 + (lane >> 2) + rr * 8;
                const uint32_t pbase = W1P + g * 4096;
#pragma unroll
                for (int nt = 0; nt < 4; nt++) {
                    const float w0 = e[nt][0] * (isc[nt][0] ? ic : im);
                    const float w1 = e[nt][1] * (isc[nt][1] ? ic : im);
                    const uint32_t byte = (uint32_t)r_loc * 64 + (uint32_t)(nt * 8 + lq * 2) * 2;
                    const uint32_t hh = pk2(w0, w1);
                    asm volatile("st.shared.b32 [%0], %1;"
                                 :: "r"(pbase + sw128(byte)), "r"(hh));
                }
            }
        }
    }
    __syncthreads();

    // ================= pass 2: W1 @ GT^T, two N-halves =================
#pragma unroll 1
    for (int h = 0; h < 2; h++) {
        float acc2[2][4][4];
#pragma unroll
        for (int i = 0; i < 2; i++)
#pragma unroll
            for (int j = 0; j < 4; j++)
#pragma unroll
                for (int r = 0; r < 4; r++) acc2[i][j][r] = 0.f;

#pragma unroll 1
        for (int k2 = 0; k2 < 8; k2++) {
            const int gidx = h * 8 + k2;
            asm volatile("cp.async.wait_group 1;");
            __syncthreads();
            if (gidx + 2 < 16) loadGT((gidx + 2) % 3, gidx + 2);
            asm volatile("cp.async.commit_group;");

            const uint32_t aS = W1P + k2 * 4096;
            const uint32_t bS = B1S + (gidx % 3) * 8192;
#pragma unroll
            for (int kk = 0; kk < 2; kk++) {
                uint32_t a[2][4], bfr[2][4];
#pragma unroll
                for (int mt = 0; mt < 2; mt++) {
                    uint32_t byte = (uint32_t)(wm * 32 + mt * 16 + a_row) * 64
                                  + (uint32_t)(kk * 16 + a_k8) * 2;
                    uint32_t ad = aS + sw128(byte);
                    asm volatile(
                        "ldmatrix.sync.aligned.m8n8.x4.shared.b16 {%0,%1,%2,%3}, [%4];"
                        : "=r"(a[mt][0]), "=r"(a[mt][1]), "=r"(a[mt][2]), "=r"(a[mt][3])
                        : "r"(ad));
                }
#pragma unroll
                for (int np = 0; np < 2; np++) {
                    uint32_t byte = (uint32_t)(wn * 32 + np * 16 + b_row) * 64
                                  + (uint32_t)(kk * 16 + b_k8) * 2;
                    uint32_t bd = bS + sw128(byte);
                    asm volatile(
                        "ldmatrix.sync.aligned.m8n8.x4.shared.b16 {%0,%1,%2,%3}, [%4];"
                        : "=r"(bfr[np][0]), "=r"(bfr[np][1]), "=r"(bfr[np][2]), "=r"(bfr[np][3])
                        : "r"(bd));
                }
#pragma unroll
                for (int mt = 0; mt < 2; mt++)
#pragma unroll
                    for (int nt = 0; nt < 4; nt++) {
                        const uint32_t b0 = bfr[nt >> 1][(nt & 1) * 2];
                        const uint32_t b1v = bfr[nt >> 1][(nt & 1) * 2 + 1];
                        asm volatile(
                            "mma.sync.aligned.m16n8k16.row.col.f32.bf16.bf16.f32 "
                            "{%0,%1,%2,%3}, {%4,%5,%6,%7}, {%8,%9}, {%0,%1,%2,%3};"
                            : "+f"(acc2[mt][nt][0]), "+f"(acc2[mt][nt][1]),
                              "+f"(acc2[mt][nt][2]), "+f"(acc2[mt][nt][3])
                            : "r"(a[mt][0]), "r"(a[mt][1]), "r"(a[mt][2]), "r"(a[mt][3]),
                              "r"(b0), "r"(b1v));
                    }
            }
            __syncthreads();
        }

        // ---- epilogue half h: softmax2 + column accumulation ----
        float addv[4][2]; bool isc[4][2];
#pragma unroll
        for (int nt = 0; nt < 4; nt++)
#pragma unroll
            for (int q = 0; q < 2; q++) {
                const int t = nt * 8 + lq * 2 + q;
                addv[nt][q] = beta2[h * 128 + wn * 32 + t] + smk[t];
                isc[nt][q]  = (t < 19);
            }
        float colacc[4][2];
#pragma unroll
        for (int nt = 0; nt < 4; nt++) { colacc[nt][0] = 0.f; colacc[nt][1] = 0.f; }

#pragma unroll
        for (int mt = 0; mt < 2; mt++) {
#pragma unroll
            for (int rr = 0; rr < 2; rr++) {
                float v[4][2];
                float mc = -1e30f, mmx = -1e30f;
#pragma unroll
                for (int nt = 0; nt < 4; nt++)
#pragma unroll
                    for (int q = 0; q < 2; q++) {
                        v[nt][q] = acc2[mt][nt][rr * 2 + q] + addv[nt][q];
                        if (isc[nt][q]) mc = fmaxf(mc, v[nt][q]);
                        else            mmx = fmaxf(mmx, v[nt][q]);
                    }
                mc  = fmaxf(mc,  __shfl_xor_sync(0xffffffffu, mc, 1));
                mc  = fmaxf(mc,  __shfl_xor_sync(0xffffffffu, mc, 2));
                mmx = fmaxf(mmx, __shfl_xor_sync(0xffffffffu, mmx, 1));
                mmx = fmaxf(mmx, __shfl_xor_sync(0xffffffffu, mmx, 2));

                float e[4][2];
                float sc = 0.f, sm = 0.f;
#pragma unroll
                for (int nt = 0; nt < 4; nt++)
#pragma unroll
                    for (int q = 0; q < 2; q++) {
                        const float ev = __expf(v[nt][q] - (isc[nt][q] ? mc : mmx));
                        e[nt][q] = ev;
                        if (isc[nt][q]) sc += ev; else sm += ev;
                    }
                sc += __shfl_xor_sync(0xffffffffu, sc, 1);
                sc += __shfl_xor_sync(0xffffffffu, sc, 2);
                sm += __shfl_xor_sync(0xffffffffu, sm, 1);
                sm += __shfl_xor_sync(0xffffffffu, sm, 2);
                const float ic = 1.f / sc, im = 1.f / sm;
#pragma unroll
                for (int nt = 0; nt < 4; nt++)
#pragma unroll
                    for (int q = 0; q < 2; q++)
                        colacc[nt][q] += e[nt][q] * (isc[nt][q] ? ic : im);
            }
        }
#pragma unroll
        for (int st = 4; st < 32; st <<= 1)
#pragma unroll
            for (int nt = 0; nt < 4; nt++) {
                colacc[nt][0] += __shfl_xor_sync(0xffffffffu, colacc[nt][0], st);
                colacc[nt][1] += __shfl_xor_sync(0xffffffffu, colacc[nt][1], st);
            }
        if (lane < 4) {
#pragma unroll
            for (int nt = 0; nt < 4; nt++) {
                spart[wm][h * 128 + wn * 32 + nt * 8 + lane * 2]     = colacc[nt][0];
                spart[wm][h * 128 + wn * 32 + nt * 8 + lane * 2 + 1] = colacc[nt][1];
            }
        }
    }

    __syncthreads();
    if (tid < NP)
        part[(size_t)tile * NP + tid] = spart[0][tid] + spart[1][tid];
}

// ===================================================================
// final: Wsum = sum of 32 tile parts; out = Wsum . VWo / pmsum + S*bo/pmsum
// ===================================================================
__global__ void final_kernel(const float* __restrict__ cbo, const float* __restrict__ mbo,
                             float* __restrict__ out)
{
    __shared__ float ws[NP];
    const int b = blockIdx.x, tid = threadIdx.x;
    if (tid < NP) {
        float s = 0.f;
#pragma unroll
        for (int p = 0; p < 32; p++) s += g_part[(size_t)(b * 32 + p) * NP + tid];
        ws[tid] = s;
    }
    __syncthreads();
    const int c = tid;   // 512 threads
    float oc = 0.f, om = 0.f;
#pragma unroll 1
    for (int g = 0; g < 8; g++) {
#pragma unroll
        for (int t = 0; t < 19; t++) oc += ws[g * 32 + t] * g_VW[(size_t)(g * 32 + t) * 512 + c];
#pragma unroll
        for (int t = 19; t < 29; t++) om += ws[g * 32 + t] * g_VW[(size_t)(g * 32 + t) * 512 + c];
    }
    const float invp = 1.f / g_pmsum[b];
    oc = (oc + 2048.f * cbo[c]) * invp;
    om = (om + 2048.f * mbo[c]) * invp;
    out[b * 512 + c] = oc;
    out[BATCH * 512 + b * 512 + c] = oc - om;
}

// ===================================================================
extern "C" void kernel_launch(void* const* d_in, const int* in_sizes, int n_in,
                              void* d_out, int out_size)
{
    const float* emb   = (const float*)d_in[0];
    const int*   emask = (const int*)d_in[1];
    const int*   pmask = (const int*)d_in[2];
    // d_in[3] frame_mask cancels in softmax — unused
    const int*   cmask = (const int*)d_in[4];
    const int*   mmask = (const int*)d_in[5];
    const float* W_lin = (const float*)d_in[6];
    const float* b_lin = (const float*)d_in[7];
    const float* ctab  = (const float*)d_in[8];
    const float* mtab  = (const float*)d_in[9];
    const float* cWq = (const float*)d_in[10]; const float* cbq = (const float*)d_in[11];
    const float* cWk = (const float*)d_in[12]; const float* cbk = (const float*)d_in[13];
    const float* cWv = (const float*)d_in[14]; const float* cbv = (const float*)d_in[15];
    const float* cWo = (const float*)d_in[16]; const float* cbo = (const float*)d_in[17];
    const float* mWq = (const float*)d_in[18]; const float* mbq = (const float*)d_in[19];
    const float* mWk = (const float*)d_in[20]; const float* mbk = (const float*)d_in[21];
    const float* mWv = (const float*)d_in[22]; const float* mbv = (const float*)d_in[23];
    const float* mWo = (const float*)d_in[24]; const float* mbo = (const float*)d_in[25];
    float* out = (float*)d_out;

    __nv_bfloat16 *pP1T, *pGT;
    float *pbeta1, *pbeta2, *pPart;
    cudaGetSymbolAddress((void**)&pP1T,   g_P1T);
    cudaGetSymbolAddress((void**)&pGT,    g_GT);
    cudaGetSymbolAddress((void**)&pbeta1, g_beta1);
    cudaGetSymbolAddress((void**)&pbeta2, g_beta2);
    cudaGetSymbolAddress((void**)&pPart,  g_part);

    cudaFuncSetAttribute((const void*)fused_all,
                         cudaFuncAttributeMaxDynamicSharedMemorySize, SMEM_FUSED);

    // prep chain (3 launches, by dependency level)
    prep_ab<<<94, 512>>>(ctab, mtab, cWk, cbk, cWv, cbv, mWk, mbk, mWv, mbv,
                         b_lin, cWq, cbq, mWq, mbq, cbo, mbo, emask, pmask);
    prep_b<<<769, 512>>>(cWq, mWq, cWo, mWo);
    prep_c<<<144, 256, PREPC_SMEM>>>(W_lin);

    // fused pass 1 + pass 2 (2 CTAs/SM)
    fused_all<<<1024, 256, SMEM_FUSED>>>(emb, pP1T, pGT, pbeta1, pbeta2,
                                         cmask, mmask, pPart);

    final_kernel<<<BATCH, 512>>>(cbo, mbo, out);
}

// round 11
// speedup vs baseline: 1.3469x; 1.0744x over previous
#include <cuda_runtime.h>
#include <cuda_bf16.h>
#include <cstdint>

// ---------------- problem constants ----------------
#define BATCH 32
#define SEQ   2048
#define NROWS (BATCH*SEQ)   // 65536
#define NP 256              // packed columns: 8 head-groups x (19 cult | 10 moral | 3 pad)

// ---------------- scratch (device globals) ----------------
__device__ __nv_bfloat16 g_P1T[NP*1024];               // B of pass 1: [n][k]
__device__ __nv_bfloat16 g_GT[NP*NP];                  // B of pass 2: GT[n_out][n_in]
__device__ float g_KQ[512*NP];                         // KQ[e][n] (includes 1/8)
__device__ float g_VW[NP*512];                         // VWo[n][f]
__device__ float g_beta1[NP], g_beta2[NP];
__device__ float g_Kc[19*512], g_Vc[19*512], g_Km[10*512], g_Vm[10*512];
__device__ float g_bf1[1024];
__device__ float g_bf2c[512], g_bf2m[512];
__device__ float g_pmsum[BATCH];
__device__ float g_part[1024*NP];

__device__ __forceinline__ uint32_t smem_u32(const void* p) {
    return (uint32_t)__cvta_generic_to_shared(p);
}
__device__ __forceinline__ void cp_async16(uint32_t dst, const void* src) {
    asm volatile("cp.async.cg.shared.global [%0], [%1], 16;" :: "r"(dst), "l"(src));
}
__device__ __forceinline__ uint32_t sw128(uint32_t b) { return b ^ ((b >> 3) & 0x70u); }
__device__ __forceinline__ uint32_t pk2(float x, float y) {
    __nv_bfloat162 h = __floats2bfloat162_rn(x, y);
    return *reinterpret_cast<uint32_t*>(&h);
}

// ===================================================================
// prep level A: K/V head tables + folded bias rows + pmsum
// ===================================================================
__global__ void prep_ab(const float* __restrict__ ctab, const float* __restrict__ mtab,
                        const float* __restrict__ cWk, const float* __restrict__ cbk,
                        const float* __restrict__ cWv, const float* __restrict__ cbv,
                        const float* __restrict__ mWk, const float* __restrict__ mbk,
                        const float* __restrict__ mWv, const float* __restrict__ mbv,
                        const float* __restrict__ b_lin,
                        const float* __restrict__ cWq, const float* __restrict__ cbq,
                        const float* __restrict__ mWq, const float* __restrict__ mbq,
                        const float* __restrict__ cbo, const float* __restrict__ mbo,
                        const int* __restrict__ em, const int* __restrict__ pmask)
{
    const int id = blockIdx.x;
    const int tid = threadIdx.x;
    if (id < 62) {
        const float* arow; const float* W; const float* bb; float* out;
        if      (id < 19)  { arow = ctab + id * 512;        W = cWk; bb = cbk; out = g_Kc + id * 512; }
        else if (id < 38)  { arow = ctab + (id - 19) * 512; W = cWv; bb = cbv; out = g_Vc + (id - 19) * 512; }
        else if (id < 48)  { arow = mtab + (id - 38) * 512; W = mWk; bb = mbk; out = g_Km + (id - 38) * 512; }
        else if (id < 58)  { arow = mtab + (id - 48) * 512; W = mWv; bb = mbv; out = g_Vm + (id - 48) * 512; }
        else if (id == 58) { arow = b_lin; W = cWq; bb = cbq; out = g_bf1; }
        else if (id == 59) { arow = b_lin; W = mWq; bb = mbq; out = g_bf1 + 512; }
        else if (id == 60) { arow = cbo;   W = cWq; bb = cbq; out = g_bf2c; }
        else               { arow = mbo;   W = mWq; bb = mbq; out = g_bf2m; }

        __shared__ float sA[512];
        sA[tid] = arow[tid];
        __syncthreads();
        float acc = bb[tid];
        for (int k = 0; k < 512; k++) acc += sA[k] * W[k * 512 + tid];
        out[tid] = acc;
    } else {
        const int b = id - 62;
        __shared__ int sred[16];
        int cnt = 0;
        for (int s = tid; s < SEQ; s += 512) cnt += em[b * SEQ + s] * pmask[b * SEQ + s];
#pragma unroll
        for (int st = 16; st; st >>= 1) cnt += __shfl_xor_sync(0xffffffffu, cnt, st);
        if ((tid & 31) == 0) sred[tid >> 5] = cnt;
        __syncthreads();
        if (tid == 0) {
            int tot = 0;
            for (int w = 0; w < 16; w++) tot += sred[w];
            g_pmsum[b] = (float)tot;
        }
    }
}

// ===================================================================
// prep level B: kq (ids 0..511), vwo (ids 512..767), betas (id 768)
// ===================================================================
__global__ void prep_b(const float* __restrict__ cWq, const float* __restrict__ mWq,
                       const float* __restrict__ cWo, const float* __restrict__ mWo)
{
    const int id = blockIdx.x;
    const int tid = threadIdx.x;
    if (id < 512) {
        const int e = id;
        __shared__ float swc[512], swm[512];
        swc[tid] = cWq[e * 512 + tid];
        swm[tid] = mWq[e * 512 + tid];
        __syncthreads();
        if (tid < 256) {
            const int n = tid, g = n >> 5, t = n & 31;
            float acc = 0.f;
            if (t < 19) {
                for (int d = 0; d < 64; d++) acc += swc[g * 64 + d] * g_Kc[t * 512 + g * 64 + d];
            } else if (t < 29) {
                const int j = t - 19;
                for (int d = 0; d < 64; d++) acc += swm[g * 64 + d] * g_Km[j * 512 + g * 64 + d];
            }
            g_KQ[e * 256 + n] = acc * 0.125f;
        }
    } else if (id < 768) {
        const int n = id - 512, g = n >> 5, t = n & 31;
        __shared__ float sv[64];
        const bool pad = (t >= 29);
        const float* V; const float* Wo; int j;
        if (t < 19)      { V = g_Vc; Wo = cWo; j = t; }
        else if (t < 29) { V = g_Vm; Wo = mWo; j = t - 19; }
        else             { V = g_Vc; Wo = cWo; j = 0; }
        const int f = tid;
        if (f < 64) sv[f] = V[j * 512 + g * 64 + f];
        __syncthreads();
        float acc = 0.f;
        for (int e = 0; e < 64; e++) acc += sv[e] * Wo[(g * 64 + e) * 512 + f];
        g_VW[n * 512 + f] = pad ? 0.f : acc;
    } else if (tid < 256) {
        const int n = tid, g = n >> 5, t = n & 31;
        float b1 = 0.f, b2 = 0.f;
        if (t < 19) {
            for (int d = 0; d < 64; d++) {
                const float kk = g_Kc[t * 512 + g * 64 + d];
                b1 += g_bf1[g * 64 + d] * kk;
                b2 += g_bf2c[g * 64 + d] * kk;
            }
        } else if (t < 29) {
            const int j = t - 19;
            for (int d = 0; d < 64; d++) {
                const float kk = g_Km[j * 512 + g * 64 + d];
                b1 += g_bf1[512 + g * 64 + d] * kk;
                b2 += g_bf2m[g * 64 + d] * kk;
            }
        }
        g_beta1[n] = b1 * 0.125f;
        g_beta2[n] = b2 * 0.125f;
    }
}

// ===================================================================
// prep level C (256 threads, dynamic smem):
//   ids 0..127  : P1T[n][k0..k0+8) = W_lin @ KQ
//   ids 128..143: GT 64x64 tile = mask ∘ (VW @ KQ)^T
// ===================================================================
#define PREPC_SMEM (2 * 64 * 65 * 4)

__global__ void prep_c(const float* __restrict__ W_lin)
{
    extern __shared__ float shd[];
    const int id = blockIdx.x;
    const int tid = threadIdx.x;   // 256
    if (id < 128) {
        const int k0 = id * 8;
        float* sw = shd;           // [8][512]
        for (int i = tid; i < 8 * 512; i += 256)
            sw[i] = W_lin[(size_t)(k0 + (i >> 9)) * 512 + (i & 511)];
        __syncthreads();
        float acc[8] = {0, 0, 0, 0, 0, 0, 0, 0};
        for (int e = 0; e < 512; e++) {
            const float kq = g_KQ[e * 256 + tid];
#pragma unroll
            for (int r = 0; r < 8; r++) acc[r] += sw[r * 512 + e] * kq;
        }
#pragma unroll
        for (int r = 0; r < 8; r++)
            g_P1T[(size_t)tid * 1024 + k0 + r] = __float2bfloat16(acc[r]);
    } else {
        const int bt = id - 128;
        const int np0 = (bt & 3) * 64;
        const int no0 = (bt >> 2) * 64;
        float* As = shd;               // [64][65]
        float* Bs = shd + 64 * 65;     // [64][65]
        float accv[4][4];
#pragma unroll
        for (int i = 0; i < 4; i++)
#pragma unroll
            for (int j = 0; j < 4; j++) accv[i][j] = 0.f;

        const int tx = tid & 15, ty = tid >> 4;
        for (int k0 = 0; k0 < 512; k0 += 64) {
            for (int i = tid; i < 64 * 16; i += 256) {
                const int r = i >> 4, c4 = i & 15;
                const float4 v = *(const float4*)&g_VW[(size_t)(np0 + r) * 512 + k0 + c4 * 4];
                float* d = &As[r * 65 + c4 * 4];
                d[0] = v.x; d[1] = v.y; d[2] = v.z; d[3] = v.w;
            }
            for (int i = tid; i < 64 * 16; i += 256) {
                const int r = i >> 4, c4 = i & 15;
                const float4 v = *(const float4*)&g_KQ[(size_t)(k0 + r) * 256 + no0 + c4 * 4];
                float* d = &Bs[r * 65 + c4 * 4];
                d[0] = v.x; d[1] = v.y; d[2] = v.z; d[3] = v.w;
            }
            __syncthreads();
#pragma unroll 8
            for (int kk = 0; kk < 64; kk++) {
                float av[4], bv[4];
#pragma unroll
                for (int i = 0; i < 4; i++) av[i] = As[(ty * 4 + i) * 65 + kk];
#pragma unroll
                for (int j = 0; j < 4; j++) bv[j] = Bs[kk * 65 + tx * 4 + j];
#pragma unroll
                for (int i = 0; i < 4; i++)
#pragma unroll
                    for (int j = 0; j < 4; j++) accv[i][j] += av[i] * bv[j];
            }
            __syncthreads();
        }
#pragma unroll
        for (int i = 0; i < 4; i++) {
            const int np = np0 + ty * 4 + i, tnp = np & 31;
#pragma unroll
            for (int j = 0; j < 4; j++) {
                const int no = no0 + tx * 4 + j, tno = no & 31;
                const bool ok = (tno < 29) && (tnp < 29) && ((tno < 19) == (tnp < 19));
                g_GT[(size_t)no * 256 + np] = __float2bfloat16(ok ? accv[i][j] : 0.f);
            }
        }
    }
}

// ===================================================================
// Fused kernel: one CTA per 64-row tile, 256 threads (8 warps, 2m x 4n),
// TWO CTAs per SM. A-path fully async: cp.async fp32 staging -> cvt -> bf16 panel.
//  Pass 1: logits1 = emb @ P1T^T, BK=32, softmax -> W1 SMEM panels.
//  Pass 2: logits2 = W1 @ GT^T (GT cp.async streamed), softmax, colsum -> part.
// SMEM: APAN=0 (2x4KB bf16), AF32=8192 (2x8KB fp32), B1S=24576 (3x16KB; GT 3x8KB reuse),
//       W1P=73728 (8x4KB).  Total 105.5KB -> 2 CTAs/SM.
// ===================================================================
#define SMEM_FUSED (106496 + 1024)

__global__ __launch_bounds__(256, 2)
void fused_all(const float* __restrict__ Af,
               const __nv_bfloat16* __restrict__ P1T,
               const __nv_bfloat16* __restrict__ GT,
               const float* __restrict__ beta1, const float* __restrict__ beta2,
               const int* __restrict__ cmask, const int* __restrict__ mmask,
               float* __restrict__ part)
{
    extern __shared__ __align__(16) char dsm[];
    const uint32_t sbase = (smem_u32(dsm) + 1023u) & ~1023u;
    const uint32_t APAN = sbase;            // 2 x 4KB bf16 A panels (64 rows x 64B)
    const uint32_t AF32 = sbase + 8192;     // 2 x 8KB fp32 A stages (64 rows x 128B)
    const uint32_t B1S  = sbase + 24576;    // 3 x 16KB B1 stages / 3 x 8KB GT stages
    const uint32_t W1P  = sbase + 73728;    // 8 x 4KB W1 panels
    __shared__ float smk[32];
    __shared__ float spart[2][NP];

    const int tid  = threadIdx.x;
    const int warp = tid >> 5, lane = tid & 31;
    const int wm = warp >> 2;        // 0..1 -> m offset *32
    const int wn = warp & 3;         // 0..3 -> n offset *64 (pass1) / *32 (pass2)
    const int tile = blockIdx.x;     // 1024 tiles of 64 rows
    const int m0 = tile * 64;
    const int b  = tile >> 5;
    const int lq = lane & 3;

    if (tid < 32) {
        float v;
        if (tid < 19)      v = (float)cmask[b * 19 + tid];
        else if (tid < 29) v = (float)mmask[b * 10 + tid - 19];
        else               v = -1e30f;
        smk[tid] = v;
    }

    const int a_row = lane & 15;
    const int a_k8  = (lane >> 4) << 3;
    const int b_row = (lane & 7) | ((lane >> 4) << 3);
    const int b_k8  = ((lane >> 3) & 1) << 3;

    // ================= pass 1 mainloop (BK=32, 32 iterations) =================
    float acc1[2][8][4];
#pragma unroll
    for (int i = 0; i < 2; i++)
#pragma unroll
        for (int j = 0; j < 8; j++)
#pragma unroll
            for (int r = 0; r < 4; r++) acc1[i][j][r] = 0.f;

    // A fp32 stage: 64 rows x 32 cols = 8KB; 512 x 16B chunks; 2 per thread
    auto loadA = [&](int s, int kt) {
        const uint32_t ab = AF32 + s * 8192;
#pragma unroll
        for (int t = 0; t < 2; t++) {
            int id  = tid + t * 256;
            int row = id >> 3, c = id & 7;    // 64 rows x 8 chunks
            cp_async16(ab + row * 128 + c * 16,
                       Af + (size_t)(m0 + row) * 1024 + kt * 32 + c * 4);
        }
    };
    // cvt: AF32 stage -> bf16 swizzled panel. thread: row=tid>>2, 8 floats at (tid&3)*8
    auto cvtA = [&](int s) {
        const uint32_t fb = AF32 + s * 8192 + (uint32_t)(tid >> 2) * 128 + (uint32_t)(tid & 3) * 32;
        float4 r0, r1;
        asm volatile("ld.shared.v4.f32 {%0,%1,%2,%3}, [%4];"
                     : "=f"(r0.x), "=f"(r0.y), "=f"(r0.z), "=f"(r0.w) : "r"(fb));
        asm volatile("ld.shared.v4.f32 {%0,%1,%2,%3}, [%4];"
                     : "=f"(r1.x), "=f"(r1.y), "=f"(r1.z), "=f"(r1.w) : "r"(fb + 16));
        const uint32_t byte = (uint32_t)(tid >> 2) * 64 + (uint32_t)(tid & 3) * 16;
        const uint32_t a0 = APAN + s * 4096 + sw128(byte);
        uint32_t h0 = pk2(r0.x, r0.y), h1 = pk2(r0.z, r0.w);
        uint32_t h2 = pk2(r1.x, r1.y), h3 = pk2(r1.z, r1.w);
        asm volatile("st.shared.v4.b32 [%0], {%1,%2,%3,%4};"
                     :: "r"(a0), "r"(h0), "r"(h1), "r"(h2), "r"(h3));
    };
    auto loadB1 = [&](int s, int kt) {
        const uint32_t bb = B1S + s * 16384;
        const __nv_bfloat16* Bg = P1T + kt * 32;
#pragma unroll
        for (int t = 0; t < 4; t++) {
            int id  = tid + t * 256;
            int row = id >> 2, c = id & 3;   // 256 rows x 4 chunks of 16B
            uint32_t byte = row * 64 + c * 16;
            cp_async16(bb + sw128(byte), Bg + (size_t)row * 1024 + c * 8);
        }
    };

    loadA(0, 0);
    loadB1(0, 0);
    asm volatile("cp.async.commit_group;");
    loadA(1, 1);
    loadB1(1, 1);
    asm volatile("cp.async.commit_group;");

    for (int kt = 0; kt < 32; kt++) {
        asm volatile("cp.async.wait_group 1;");
        __syncthreads();
        cvtA(kt & 1);
        __syncthreads();
        if (kt + 2 < 32) {
            loadA(kt & 1, kt + 2);              // AF32 stage freed by cvt
            loadB1((kt + 2) % 3, kt + 2);
        }
        asm volatile("cp.async.commit_group;");

        const uint32_t aS = APAN + (kt & 1) * 4096;
        const uint32_t bS = B1S + (kt % 3) * 16384;
#pragma unroll
        for (int kk = 0; kk < 2; kk++) {
            uint32_t a[2][4], bfr[4][4];
#pragma unroll
            for (int mt = 0; mt < 2; mt++) {
                uint32_t byte = (uint32_t)(wm * 32 + mt * 16 + a_row) * 64
                              + (uint32_t)(kk * 16 + a_k8) * 2;
                uint32_t ad = aS + sw128(byte);
                asm volatile(
                    "ldmatrix.sync.aligned.m8n8.x4.shared.b16 {%0,%1,%2,%3}, [%4];"
                    : "=r"(a[mt][0]), "=r"(a[mt][1]), "=r"(a[mt][2]), "=r"(a[mt][3])
                    : "r"(ad));
            }
#pragma unroll
            for (int np = 0; np < 4; np++) {
                uint32_t byte = (uint32_t)(wn * 64 + np * 16 + b_row) * 64
                              + (uint32_t)(kk * 16 + b_k8) * 2;
                uint32_t bd = bS + sw128(byte);
                asm volatile(
                    "ldmatrix.sync.aligned.m8n8.x4.shared.b16 {%0,%1,%2,%3}, [%4];"
                    : "=r"(bfr[np][0]), "=r"(bfr[np][1]), "=r"(bfr[np][2]), "=r"(bfr[np][3])
                    : "r"(bd));
            }
#pragma unroll
            for (int mt = 0; mt < 2; mt++)
#pragma unroll
                for (int nt = 0; nt < 8; nt++) {
                    const uint32_t b0 = bfr[nt >> 1][(nt & 1) * 2];
                    const uint32_t b1v = bfr[nt >> 1][(nt & 1) * 2 + 1];
                    asm volatile(
                        "mma.sync.aligned.m16n8k16.row.col.f32.bf16.bf16.f32 "
                        "{%0,%1,%2,%3}, {%4,%5,%6,%7}, {%8,%9}, {%0,%1,%2,%3};"
                        : "+f"(acc1[mt][nt][0]), "+f"(acc1[mt][nt][1]),
                          "+f"(acc1[mt][nt][2]), "+f"(acc1[mt][nt][3])
                        : "r"(a[mt][0]), "r"(a[mt][1]), "r"(a[mt][2]), "r"(a[mt][3]),
                          "r"(b0), "r"(b1v));
                }
        }
        __syncthreads();   // protects APAN(kt&1) until overwritten at kt+2
    }

    // ---- prefetch GT stages 0,1 (reuse B1 region) ----
    auto loadGT = [&](int s, int gidx) {
        const int h2 = gidx >> 3, k2 = gidx & 7;
        const uint32_t bb = B1S + s * 8192;
#pragma unroll
        for (int t = 0; t < 2; t++) {
            int id = tid + t * 256;
            int row = id >> 2, c = id & 3;   // 128 rows x 4 chunks
            uint32_t byte = row * 64 + c * 16;
            cp_async16(bb + sw128(byte), GT + (size_t)(h2 * 128 + row) * 256 + k2 * 32 + c * 8);
        }
    };
    loadGT(0, 0);
    asm volatile("cp.async.commit_group;");
    loadGT(1, 1);
    asm volatile("cp.async.commit_group;");

    // ================= pass-1 epilogue: softmax -> W1 panels =================
#pragma unroll
    for (int gh = 0; gh < 2; gh++) {
        const int g = wn * 2 + gh;
        float addv[4][2]; bool isc[4][2];
#pragma unroll
        for (int nt = 0; nt < 4; nt++)
#pragma unroll
            for (int q = 0; q < 2; q++) {
                const int t = nt * 8 + lq * 2 + q;
                addv[nt][q] = beta1[g * 32 + t] + smk[t];
                isc[nt][q]  = (t < 19);
            }
#pragma unroll
        for (int mt = 0; mt < 2; mt++) {
#pragma unroll
            for (int rr = 0; rr < 2; rr++) {
                float v[4][2];
                float mc = -1e30f, mmx = -1e30f;
#pragma unroll
                for (int nt = 0; nt < 4; nt++)
#pragma unroll
                    for (int q = 0; q < 2; q++) {
                        v[nt][q] = acc1[mt][gh * 4 + nt][rr * 2 + q] + addv[nt][q];
                        if (isc[nt][q]) mc = fmaxf(mc, v[nt][q]);
                        else            mmx = fmaxf(mmx, v[nt][q]);
                    }
                mc  = fmaxf(mc,  __shfl_xor_sync(0xffffffffu, mc, 1));
                mc  = fmaxf(mc,  __shfl_xor_sync(0xffffffffu, mc, 2));
                mmx = fmaxf(mmx, __shfl_xor_sync(0xffffffffu, mmx, 1));
                mmx = fmaxf(mmx, __shfl_xor_sync(0xffffffffu, mmx, 2));

                float e[4][2];
                float sc = 0.f, sm = 0.f;
#pragma unroll
                for (int nt = 0; nt < 4; nt++)
#pragma unroll
                    for (int q = 0; q < 2; q++) {
                        const float ev = __expf(v[nt][q] - (isc[nt][q] ? mc : mmx));
                        e[nt][q] = ev;
                        if (isc[nt][q]) sc += ev; else sm += ev;
                    }
                sc += __shfl_xor_sync(0xffffffffu, sc, 1);
                sc += __shfl_xor_sync(0xffffffffu, sc, 2);
                sm += __shfl_xor_sync(0xffffffffu, sm, 1);
                sm += __shfl_xor_sync(0xffffffffu, sm, 2);
                const float ic = 1.f / sc, im = 1.f / sm;

                const int r_loc = wm * 32 + mt * 16 + (lane >> 2) + rr * 8;
                const uint32_t pbase = W1P + g * 4096;
#pragma unroll
                for (int nt = 0; nt < 4; nt++) {
                    const float w0 = e[nt][0] * (isc[nt][0] ? ic : im);
                    const float w1 = e[nt][1] * (isc[nt][1] ? ic : im);
                    const uint32_t byte = (uint32_t)r_loc * 64 + (uint32_t)(nt * 8 + lq * 2) * 2;
                    const uint32_t hh = pk2(w0, w1);
                    asm volatile("st.shared.b32 [%0], %1;"
                                 :: "r"(pbase + sw128(byte)), "r"(hh));
                }
            }
        }
    }
    __syncthreads();

    // ================= pass 2: W1 @ GT^T, two N-halves =================
#pragma unroll 1
    for (int h = 0; h < 2; h++) {
        float acc2[2][4][4];
#pragma unroll
        for (int i = 0; i < 2; i++)
#pragma unroll
            for (int j = 0; j < 4; j++)
#pragma unroll
                for (int r = 0; r < 4; r++) acc2[i][j][r] = 0.f;

#pragma unroll 1
        for (int k2 = 0; k2 < 8; k2++) {
            const int gidx = h * 8 + k2;
            asm volatile("cp.async.wait_group 1;");
            __syncthreads();
            if (gidx + 2 < 16) loadGT((gidx + 2) % 3, gidx + 2);
            asm volatile("cp.async.commit_group;");

            const uint32_t aS = W1P + k2 * 4096;
            const uint32_t bS = B1S + (gidx % 3) * 8192;
#pragma unroll
            for (int kk = 0; kk < 2; kk++) {
                uint32_t a[2][4], bfr[2][4];
#pragma unroll
                for (int mt = 0; mt < 2; mt++) {
                    uint32_t byte = (uint32_t)(wm * 32 + mt * 16 + a_row) * 64
                                  + (uint32_t)(kk * 16 + a_k8) * 2;
                    uint32_t ad = aS + sw128(byte);
                    asm volatile(
                        "ldmatrix.sync.aligned.m8n8.x4.shared.b16 {%0,%1,%2,%3}, [%4];"
                        : "=r"(a[mt][0]), "=r"(a[mt][1]), "=r"(a[mt][2]), "=r"(a[mt][3])
                        : "r"(ad));
                }
#pragma unroll
                for (int np = 0; np < 2; np++) {
                    uint32_t byte = (uint32_t)(wn * 32 + np * 16 + b_row) * 64
                                  + (uint32_t)(kk * 16 + b_k8) * 2;
                    uint32_t bd = bS + sw128(byte);
                    asm volatile(
                        "ldmatrix.sync.aligned.m8n8.x4.shared.b16 {%0,%1,%2,%3}, [%4];"
                        : "=r"(bfr[np][0]), "=r"(bfr[np][1]), "=r"(bfr[np][2]), "=r"(bfr[np][3])
                        : "r"(bd));
                }
#pragma unroll
                for (int mt = 0; mt < 2; mt++)
#pragma unroll
                    for (int nt = 0; nt < 4; nt++) {
                        const uint32_t b0 = bfr[nt >> 1][(nt & 1) * 2];
                        const uint32_t b1v = bfr[nt >> 1][(nt & 1) * 2 + 1];
                        asm volatile(
                            "mma.sync.aligned.m16n8k16.row.col.f32.bf16.bf16.f32 "
                            "{%0,%1,%2,%3}, {%4,%5,%6,%7}, {%8,%9}, {%0,%1,%2,%3};"
                            : "+f"(acc2[mt][nt][0]), "+f"(acc2[mt][nt][1]),
                              "+f"(acc2[mt][nt][2]), "+f"(acc2[mt][nt][3])
                            : "r"(a[mt][0]), "r"(a[mt][1]), "r"(a[mt][2]), "r"(a[mt][3]),
                              "r"(b0), "r"(b1v));
                    }
            }
            __syncthreads();
        }

        // ---- epilogue half h: softmax2 + column accumulation ----
        float addv[4][2]; bool isc[4][2];
#pragma unroll
        for (int nt = 0; nt < 4; nt++)
#pragma unroll
            for (int q = 0; q < 2; q++) {
                const int t = nt * 8 + lq * 2 + q;
                addv[nt][q] = beta2[h * 128 + wn * 32 + t] + smk[t];
                isc[nt][q]  = (t < 19);
            }
        float colacc[4][2];
#pragma unroll
        for (int nt = 0; nt < 4; nt++) { colacc[nt][0] = 0.f; colacc[nt][1] = 0.f; }

#pragma unroll
        for (int mt = 0; mt < 2; mt++) {
#pragma unroll
            for (int rr = 0; rr < 2; rr++) {
                float v[4][2];
                float mc = -1e30f, mmx = -1e30f;
#pragma unroll
                for (int nt = 0; nt < 4; nt++)
#pragma unroll
                    for (int q = 0; q < 2; q++) {
                        v[nt][q] = acc2[mt][nt][rr * 2 + q] + addv[nt][q];
                        if (isc[nt][q]) mc = fmaxf(mc, v[nt][q]);
                        else            mmx = fmaxf(mmx, v[nt][q]);
                    }
                mc  = fmaxf(mc,  __shfl_xor_sync(0xffffffffu, mc, 1));
                mc  = fmaxf(mc,  __shfl_xor_sync(0xffffffffu, mc, 2));
                mmx = fmaxf(mmx, __shfl_xor_sync(0xffffffffu, mmx, 1));
                mmx = fmaxf(mmx, __shfl_xor_sync(0xffffffffu, mmx, 2));

                float e[4][2];
                float sc = 0.f, sm = 0.f;
#pragma unroll
                for (int nt = 0; nt < 4; nt++)
#pragma unroll
                    for (int q = 0; q < 2; q++) {
                        const float ev = __expf(v[nt][q] - (isc[nt][q] ? mc : mmx));
                        e[nt][q] = ev;
                        if (isc[nt][q]) sc += ev; else sm += ev;
                    }
                sc += __shfl_xor_sync(0xffffffffu, sc, 1);
                sc += __shfl_xor_sync(0xffffffffu, sc, 2);
                sm += __shfl_xor_sync(0xffffffffu, sm, 1);
                sm += __shfl_xor_sync(0xffffffffu, sm, 2);
                const float ic = 1.f / sc, im = 1.f / sm;
#pragma unroll
                for (int nt = 0; nt < 4; nt++)
#pragma unroll
                    for (int q = 0; q < 2; q++)
                        colacc[nt][q] += e[nt][q] * (isc[nt][q] ? ic : im);
            }
        }
#pragma unroll
        for (int st = 4; st < 32; st <<= 1)
#pragma unroll
            for (int nt = 0; nt < 4; nt++) {
                colacc[nt][0] += __shfl_xor_sync(0xffffffffu, colacc[nt][0], st);
                colacc[nt][1] += __shfl_xor_sync(0xffffffffu, colacc[nt][1], st);
            }
        if (lane < 4) {
#pragma unroll
            for (int nt = 0; nt < 4; nt++) {
                spart[wm][h * 128 + wn * 32 + nt * 8 + lane * 2]     = colacc[nt][0];
                spart[wm][h * 128 + wn * 32 + nt * 8 + lane * 2 + 1] = colacc[nt][1];
            }
        }
    }

    __syncthreads();
    if (tid < NP)
        part[(size_t)tile * NP + tid] = spart[0][tid] + spart[1][tid];
}

// ===================================================================
// final: Wsum = sum of 32 tile parts; out = Wsum . VWo / pmsum + S*bo/pmsum
// ===================================================================
__global__ void final_kernel(const float* __restrict__ cbo, const float* __restrict__ mbo,
                             float* __restrict__ out)
{
    __shared__ float ws[NP];
    const int b = blockIdx.x, tid = threadIdx.x;
    if (tid < NP) {
        float s = 0.f;
#pragma unroll
        for (int p = 0; p < 32; p++) s += g_part[(size_t)(b * 32 + p) * NP + tid];
        ws[tid] = s;
    }
    __syncthreads();
    const int c = tid;   // 512 threads
    float oc = 0.f, om = 0.f;
#pragma unroll 1
    for (int g = 0; g < 8; g++) {
#pragma unroll
        for (int t = 0; t < 19; t++) oc += ws[g * 32 + t] * g_VW[(size_t)(g * 32 + t) * 512 + c];
#pragma unroll
        for (int t = 19; t < 29; t++) om += ws[g * 32 + t] * g_VW[(size_t)(g * 32 + t) * 512 + c];
    }
    const float invp = 1.f / g_pmsum[b];
    oc = (oc + 2048.f * cbo[c]) * invp;
    om = (om + 2048.f * mbo[c]) * invp;
    out[b * 512 + c] = oc;
    out[BATCH * 512 + b * 512 + c] = oc - om;
}

// ===================================================================
extern "C" void kernel_launch(void* const* d_in, const int* in_sizes, int n_in,
                              void* d_out, int out_size)
{
    const float* emb   = (const float*)d_in[0];
    const int*   emask = (const int*)d_in[1];
    const int*   pmask = (const int*)d_in[2];
    // d_in[3] frame_mask cancels in softmax — unused
    const int*   cmask = (const int*)d_in[4];
    const int*   mmask = (const int*)d_in[5];
    const float* W_lin = (const float*)d_in[6];
    const float* b_lin = (const float*)d_in[7];
    const float* ctab  = (const float*)d_in[8];
    const float* mtab  = (const float*)d_in[9];
    const float* cWq = (const float*)d_in[10]; const float* cbq = (const float*)d_in[11];
    const float* cWk = (const float*)d_in[12]; const float* cbk = (const float*)d_in[13];
    const float* cWv = (const float*)d_in[14]; const float* cbv = (const float*)d_in[15];
    const float* cWo = (const float*)d_in[16]; const float* cbo = (const float*)d_in[17];
    const float* mWq = (const float*)d_in[18]; const float* mbq = (const float*)d_in[19];
    const float* mWk = (const float*)d_in[20]; const float* mbk = (const float*)d_in[21];
    const float* mWv = (const float*)d_in[22]; const float* mbv = (const float*)d_in[23];
    const float* mWo = (const float*)d_in[24]; const float* mbo = (const float*)d_in[25];
    float* out = (float*)d_out;

    __nv_bfloat16 *pP1T, *pGT;
    float *pbeta1, *pbeta2, *pPart;
    cudaGetSymbolAddress((void**)&pP1T,   g_P1T);
    cudaGetSymbolAddress((void**)&pGT,    g_GT);
    cudaGetSymbolAddress((void**)&pbeta1, g_beta1);
    cudaGetSymbolAddress((void**)&pbeta2, g_beta2);
    cudaGetSymbolAddress((void**)&pPart,  g_part);

    cudaFuncSetAttribute((const void*)fused_all,
                         cudaFuncAttributeMaxDynamicSharedMemorySize, SMEM_FUSED);

    // prep chain (3 launches, by dependency level)
    prep_ab<<<94, 512>>>(ctab, mtab, cWk, cbk, cWv, cbv, mWk, mbk, mWv, mbv,
                         b_lin, cWq, cbq, mWq, mbq, cbo, mbo, emask, pmask);
    prep_b<<<769, 512>>>(cWq, mWq, cWo, mWo);
    prep_c<<<144, 256, PREPC_SMEM>>>(W_lin);

    // fused pass 1 + pass 2 (2 CTAs/SM, fully async A path)
    fused_all<<<1024, 256, SMEM_FUSED>>>(emb, pP1T, pGT, pbeta1, pbeta2,
                                         cmask, mmask, pPart);

    final_kernel<<<BATCH, 512>>>(cbo, mbo, out);
}